// round 14
// baseline (speedup 1.0000x reference)
#include <cuda_runtime.h>
#include <cstdint>

// Problem shape (fixed by the dataset)
#define PK 4
#define PB 4096
#define PT 32
#define PD 128

#define PAIR_ELEMS ((size_t)PK * PB * PT * PT)   // 16,777,216  (64 MB)
#define NBR_ELEMS  ((size_t)PK * PB * PT * PD)   // 67,108,864  (256 MB)

// FINAL (converged, reproduced 4x: timed 67.6-68.1 us, ncu 71.1-73.8 us).
//
// 256-bit accesses with explicit L2 policies: semb gathers evict_last (8 MB
// table resident in L2), outputs evict_first (written once, never re-read).
// Gather loads are non-volatile so ptxas front-batches them (MLP).
//
// Roofline verdict: 448 MB compulsory output writes + ~10 MB reads at the
// measured 5.7-5.9 TB/s mixed-stream HBM3e rate = 71-74 us = the ncu band.
// Seven memory-path configurations (L2 hints, explicit policies, .wt,
// write coalescing, occupancy, MLP batching) all measured within +-1.5 us:
// the DRAM write drain is the clock and is not SM-schedulable.
__device__ __forceinline__ void ldg8_evict_last(const float* p, float* v) {
    asm("ld.global.nc.L2::evict_last.v8.b32 "
        "{%0,%1,%2,%3,%4,%5,%6,%7}, [%8];"
        : "=f"(v[0]), "=f"(v[1]), "=f"(v[2]), "=f"(v[3]),
          "=f"(v[4]), "=f"(v[5]), "=f"(v[6]), "=f"(v[7])
        : "l"(p));
}
__device__ __forceinline__ void stg8_evict_first(float* p, const float* v) {
    asm volatile("st.global.L2::evict_first.v8.b32 "
                 "[%0], {%1,%2,%3,%4,%5,%6,%7,%8};"
                 :: "l"(p),
                    "f"(v[0]), "f"(v[1]), "f"(v[2]), "f"(v[3]),
                    "f"(v[4]), "f"(v[5]), "f"(v[6]), "f"(v[7])
                 : "memory");
}

__global__ __launch_bounds__(128) void distance_layer_kernel(
    const float* __restrict__ semb,     // [K,B,D]
    const int*   __restrict__ slabels,  // [K,B]
    const int*   __restrict__ topk,     // [K,B,T]
    float* __restrict__ pos_out,        // [K,B,T,T]
    float* __restrict__ neg_out,        // [K,B,T,T]
    float* __restrict__ msk_out,        // [K,B,T,T]
    float* __restrict__ nbr_out)        // [K,B,T,D]
{
    const int kb   = blockIdx.x;        // 0 .. K*B-1
    const int k    = kb >> 12;          // B = 4096
    const int b    = kb & (PB - 1);
    const int tid  = threadIdx.x;       // 0..127
    const int warp = tid >> 5;
    const int lane = tid & 31;
    const int half = lane >> 4;         // which of 2 rows this half-warp owns
    const int l16  = lane & 15;         // position within a 512B row

    __shared__ float s_nsim[PT];
    __shared__ int   s_same[PT];
    __shared__ int   s_idx[PT];

    const float* semb_k = semb + (size_t)k * PB * PD;

    // Anchor embedding: thread covers dims [l16*8, l16*8+8)
    float a8[8];
    ldg8_evict_last(semb_k + (size_t)b * PD + l16 * 8, a8);

    const int anchor_label = slabels[k * PB + b];

    if (tid < PT) {
        const int idx = topk[((size_t)kb) * PT + tid];
        s_idx[tid]  = idx;
        s_same[tid] = (slabels[k * PB + idx] == anchor_label) ? 1 : 0;
    }
    __syncthreads();

    // ---- Gather phase: 4 warps x (4 iters x 2 rows) = 32 rows ------------
    // Loads are independent of the store+dot chain -> batched for MLP.
    float* nbr_base = nbr_out + (size_t)kb * PT * PD;
    float v[4][8];
    #pragma unroll
    for (int i = 0; i < 4; ++i) {
        const int t = warp * 8 + i * 2 + half;
        ldg8_evict_last(semb_k + (size_t)s_idx[t] * PD + l16 * 8, v[i]);
    }
    #pragma unroll
    for (int i = 0; i < 4; ++i) {
        const int t = warp * 8 + i * 2 + half;
        stg8_evict_first(nbr_base + t * PD + l16 * 8, v[i]);
        float p = v[i][0]*a8[0] + v[i][1]*a8[1] + v[i][2]*a8[2] + v[i][3]*a8[3]
                + v[i][4]*a8[4] + v[i][5]*a8[5] + v[i][6]*a8[6] + v[i][7]*a8[7];
        #pragma unroll
        for (int off = 8; off; off >>= 1)
            p += __shfl_xor_sync(0xffffffffu, p, off);
        if (l16 == 0) s_nsim[t] = p;
    }
    __syncthreads();

    // ---- Pair phase: 1024 (s,d) pairs = 128 float8 per tensor ------------
    float* pos_base = pos_out + (size_t)kb * PT * PT;
    float* neg_base = neg_out + (size_t)kb * PT * PT;
    float* msk_base = msk_out + (size_t)kb * PT * PT;

    const int s  = tid >> 2;            // 0..31
    const int d0 = (tid & 3) << 3;      // 0,8,16,24

    const int   ss = s_same[s];
    const float ns = s_nsim[s];

    float pv[8], nv[8], mv[8];
    #pragma unroll
    for (int j = 0; j < 8; ++j) {
        const int m = ss & (s_same[d0 + j] ^ 1);
        mv[j] = (float)m;
        pv[j] = m ? ns : 0.0f;
        nv[j] = m ? s_nsim[d0 + j] : 0.0f;
    }

    stg8_evict_first(pos_base + tid * 8, pv);
    stg8_evict_first(neg_base + tid * 8, nv);
    stg8_evict_first(msk_base + tid * 8, mv);
}

extern "C" void kernel_launch(void* const* d_in, const int* in_sizes, int n_in,
                              void* d_out, int out_size)
{
    (void)in_sizes; (void)n_in; (void)out_size;

    const float* semb    = (const float*)d_in[0];
    const int*   slabels = (const int*)  d_in[1];
    const int*   topk    = (const int*)  d_in[2];

    float* out = (float*)d_out;
    float* pos = out;
    float* neg = out + PAIR_ELEMS;
    float* msk = out + 2 * PAIR_ELEMS;
    float* nbr = out + 3 * PAIR_ELEMS;

    dim3 grid(PK * PB);   // 16384 CTAs
    dim3 block(128);
    distance_layer_kernel<<<grid, block>>>(semb, slabels, topk,
                                           pos, neg, msk, nbr);
}

// round 15
// speedup vs baseline: 1.0099x; 1.0099x over previous
#include <cuda_runtime.h>
#include <cstdint>

// Problem shape (fixed by the dataset)
#define PK 4
#define PB 4096
#define PT 32
#define PD 128

#define PAIR_ELEMS ((size_t)PK * PB * PT * PT)   // 16,777,216  (64 MB)
#define NBR_ELEMS  ((size_t)PK * PB * PT * PD)   // 67,108,864  (256 MB)

// FINAL (converged, reproduced 5x: timed 67.6-68.3 us, ncu 71.1-73.8 us).
//
// 256-bit accesses with explicit L2 policies: semb gathers evict_last (8 MB
// table resident in L2), outputs evict_first (written once, never re-read).
// Gather loads are non-volatile so ptxas front-batches them (MLP).
//
// Roofline verdict: 448 MB compulsory output writes + ~10 MB reads at the
// measured 5.7-5.9 TB/s mixed-stream HBM3e rate = 71-74 us = the ncu band.
// Seven memory-path configurations (L2 hints, explicit policies, .wt,
// write coalescing, occupancy, MLP batching) all measured within +-1.5 us:
// the DRAM write drain is the clock and is not SM-schedulable.
__device__ __forceinline__ void ldg8_evict_last(const float* p, float* v) {
    asm("ld.global.nc.L2::evict_last.v8.b32 "
        "{%0,%1,%2,%3,%4,%5,%6,%7}, [%8];"
        : "=f"(v[0]), "=f"(v[1]), "=f"(v[2]), "=f"(v[3]),
          "=f"(v[4]), "=f"(v[5]), "=f"(v[6]), "=f"(v[7])
        : "l"(p));
}
__device__ __forceinline__ void stg8_evict_first(float* p, const float* v) {
    asm volatile("st.global.L2::evict_first.v8.b32 "
                 "[%0], {%1,%2,%3,%4,%5,%6,%7,%8};"
                 :: "l"(p),
                    "f"(v[0]), "f"(v[1]), "f"(v[2]), "f"(v[3]),
                    "f"(v[4]), "f"(v[5]), "f"(v[6]), "f"(v[7])
                 : "memory");
}

__global__ __launch_bounds__(128) void distance_layer_kernel(
    const float* __restrict__ semb,     // [K,B,D]
    const int*   __restrict__ slabels,  // [K,B]
    const int*   __restrict__ topk,     // [K,B,T]
    float* __restrict__ pos_out,        // [K,B,T,T]
    float* __restrict__ neg_out,        // [K,B,T,T]
    float* __restrict__ msk_out,        // [K,B,T,T]
    float* __restrict__ nbr_out)        // [K,B,T,D]
{
    const int kb   = blockIdx.x;        // 0 .. K*B-1
    const int k    = kb >> 12;          // B = 4096
    const int b    = kb & (PB - 1);
    const int tid  = threadIdx.x;       // 0..127
    const int warp = tid >> 5;
    const int lane = tid & 31;
    const int half = lane >> 4;         // which of 2 rows this half-warp owns
    const int l16  = lane & 15;         // position within a 512B row

    __shared__ float s_nsim[PT];
    __shared__ int   s_same[PT];
    __shared__ int   s_idx[PT];

    const float* semb_k = semb + (size_t)k * PB * PD;

    // Anchor embedding: thread covers dims [l16*8, l16*8+8)
    float a8[8];
    ldg8_evict_last(semb_k + (size_t)b * PD + l16 * 8, a8);

    const int anchor_label = slabels[k * PB + b];

    if (tid < PT) {
        const int idx = topk[((size_t)kb) * PT + tid];
        s_idx[tid]  = idx;
        s_same[tid] = (slabels[k * PB + idx] == anchor_label) ? 1 : 0;
    }
    __syncthreads();

    // ---- Gather phase: 4 warps x (4 iters x 2 rows) = 32 rows ------------
    // Loads are independent of the store+dot chain -> batched for MLP.
    float* nbr_base = nbr_out + (size_t)kb * PT * PD;
    float v[4][8];
    #pragma unroll
    for (int i = 0; i < 4; ++i) {
        const int t = warp * 8 + i * 2 + half;
        ldg8_evict_last(semb_k + (size_t)s_idx[t] * PD + l16 * 8, v[i]);
    }
    #pragma unroll
    for (int i = 0; i < 4; ++i) {
        const int t = warp * 8 + i * 2 + half;
        stg8_evict_first(nbr_base + t * PD + l16 * 8, v[i]);
        float p = v[i][0]*a8[0] + v[i][1]*a8[1] + v[i][2]*a8[2] + v[i][3]*a8[3]
                + v[i][4]*a8[4] + v[i][5]*a8[5] + v[i][6]*a8[6] + v[i][7]*a8[7];
        #pragma unroll
        for (int off = 8; off; off >>= 1)
            p += __shfl_xor_sync(0xffffffffu, p, off);
        if (l16 == 0) s_nsim[t] = p;
    }
    __syncthreads();

    // ---- Pair phase: 1024 (s,d) pairs = 128 float8 per tensor ------------
    float* pos_base = pos_out + (size_t)kb * PT * PT;
    float* neg_base = neg_out + (size_t)kb * PT * PT;
    float* msk_base = msk_out + (size_t)kb * PT * PT;

    const int s  = tid >> 2;            // 0..31
    const int d0 = (tid & 3) << 3;      // 0,8,16,24

    const int   ss = s_same[s];
    const float ns = s_nsim[s];

    float pv[8], nv[8], mv[8];
    #pragma unroll
    for (int j = 0; j < 8; ++j) {
        const int m = ss & (s_same[d0 + j] ^ 1);
        mv[j] = (float)m;
        pv[j] = m ? ns : 0.0f;
        nv[j] = m ? s_nsim[d0 + j] : 0.0f;
    }

    stg8_evict_first(pos_base + tid * 8, pv);
    stg8_evict_first(neg_base + tid * 8, nv);
    stg8_evict_first(msk_base + tid * 8, mv);
}

extern "C" void kernel_launch(void* const* d_in, const int* in_sizes, int n_in,
                              void* d_out, int out_size)
{
    (void)in_sizes; (void)n_in; (void)out_size;

    const float* semb    = (const float*)d_in[0];
    const int*   slabels = (const int*)  d_in[1];
    const int*   topk    = (const int*)  d_in[2];

    float* out = (float*)d_out;
    float* pos = out;
    float* neg = out + PAIR_ELEMS;
    float* msk = out + 2 * PAIR_ELEMS;
    float* nbr = out + 3 * PAIR_ELEMS;

    dim3 grid(PK * PB);   // 16384 CTAs
    dim3 block(128);
    distance_layer_kernel<<<grid, block>>>(semb, slabels, topk,
                                           pos, neg, msk, nbr);
}

// round 16
// speedup vs baseline: 1.0206x; 1.0105x over previous
#include <cuda_runtime.h>
#include <cstdint>

// Problem shape (fixed by the dataset)
#define PK 4
#define PB 4096
#define PT 32
#define PD 128

#define PAIR_ELEMS ((size_t)PK * PB * PT * PT)   // 16,777,216  (64 MB)
#define NBR_ELEMS  ((size_t)PK * PB * PT * PD)   // 67,108,864  (256 MB)

// FINAL (converged, reproduced 6x: timed 67.6-68.3 us, ncu 71.1-73.8 us).
//
// 256-bit accesses with explicit L2 policies: semb gathers evict_last (8 MB
// table resident in L2), outputs evict_first (written once, never re-read).
// Gather loads are non-volatile so ptxas front-batches them (MLP).
//
// Roofline verdict: 448 MB compulsory output writes + ~10 MB reads at the
// measured 5.7-5.9 TB/s mixed-stream HBM3e rate = 71-74 us = the ncu band.
// Seven memory-path configurations (L2 hints, explicit policies, .wt,
// write coalescing, occupancy, MLP batching) all measured within +-1.5 us:
// the DRAM write drain is the clock and is not SM-schedulable.
__device__ __forceinline__ void ldg8_evict_last(const float* p, float* v) {
    asm("ld.global.nc.L2::evict_last.v8.b32 "
        "{%0,%1,%2,%3,%4,%5,%6,%7}, [%8];"
        : "=f"(v[0]), "=f"(v[1]), "=f"(v[2]), "=f"(v[3]),
          "=f"(v[4]), "=f"(v[5]), "=f"(v[6]), "=f"(v[7])
        : "l"(p));
}
__device__ __forceinline__ void stg8_evict_first(float* p, const float* v) {
    asm volatile("st.global.L2::evict_first.v8.b32 "
                 "[%0], {%1,%2,%3,%4,%5,%6,%7,%8};"
                 :: "l"(p),
                    "f"(v[0]), "f"(v[1]), "f"(v[2]), "f"(v[3]),
                    "f"(v[4]), "f"(v[5]), "f"(v[6]), "f"(v[7])
                 : "memory");
}

__global__ __launch_bounds__(128) void distance_layer_kernel(
    const float* __restrict__ semb,     // [K,B,D]
    const int*   __restrict__ slabels,  // [K,B]
    const int*   __restrict__ topk,     // [K,B,T]
    float* __restrict__ pos_out,        // [K,B,T,T]
    float* __restrict__ neg_out,        // [K,B,T,T]
    float* __restrict__ msk_out,        // [K,B,T,T]
    float* __restrict__ nbr_out)        // [K,B,T,D]
{
    const int kb   = blockIdx.x;        // 0 .. K*B-1
    const int k    = kb >> 12;          // B = 4096
    const int b    = kb & (PB - 1);
    const int tid  = threadIdx.x;       // 0..127
    const int warp = tid >> 5;
    const int lane = tid & 31;
    const int half = lane >> 4;         // which of 2 rows this half-warp owns
    const int l16  = lane & 15;         // position within a 512B row

    __shared__ float s_nsim[PT];
    __shared__ int   s_same[PT];
    __shared__ int   s_idx[PT];

    const float* semb_k = semb + (size_t)k * PB * PD;

    // Anchor embedding: thread covers dims [l16*8, l16*8+8)
    float a8[8];
    ldg8_evict_last(semb_k + (size_t)b * PD + l16 * 8, a8);

    const int anchor_label = slabels[k * PB + b];

    if (tid < PT) {
        const int idx = topk[((size_t)kb) * PT + tid];
        s_idx[tid]  = idx;
        s_same[tid] = (slabels[k * PB + idx] == anchor_label) ? 1 : 0;
    }
    __syncthreads();

    // ---- Gather phase: 4 warps x (4 iters x 2 rows) = 32 rows ------------
    // Loads are independent of the store+dot chain -> batched for MLP.
    float* nbr_base = nbr_out + (size_t)kb * PT * PD;
    float v[4][8];
    #pragma unroll
    for (int i = 0; i < 4; ++i) {
        const int t = warp * 8 + i * 2 + half;
        ldg8_evict_last(semb_k + (size_t)s_idx[t] * PD + l16 * 8, v[i]);
    }
    #pragma unroll
    for (int i = 0; i < 4; ++i) {
        const int t = warp * 8 + i * 2 + half;
        stg8_evict_first(nbr_base + t * PD + l16 * 8, v[i]);
        float p = v[i][0]*a8[0] + v[i][1]*a8[1] + v[i][2]*a8[2] + v[i][3]*a8[3]
                + v[i][4]*a8[4] + v[i][5]*a8[5] + v[i][6]*a8[6] + v[i][7]*a8[7];
        #pragma unroll
        for (int off = 8; off; off >>= 1)
            p += __shfl_xor_sync(0xffffffffu, p, off);
        if (l16 == 0) s_nsim[t] = p;
    }
    __syncthreads();

    // ---- Pair phase: 1024 (s,d) pairs = 128 float8 per tensor ------------
    float* pos_base = pos_out + (size_t)kb * PT * PT;
    float* neg_base = neg_out + (size_t)kb * PT * PT;
    float* msk_base = msk_out + (size_t)kb * PT * PT;

    const int s  = tid >> 2;            // 0..31
    const int d0 = (tid & 3) << 3;      // 0,8,16,24

    const int   ss = s_same[s];
    const float ns = s_nsim[s];

    float pv[8], nv[8], mv[8];
    #pragma unroll
    for (int j = 0; j < 8; ++j) {
        const int m = ss & (s_same[d0 + j] ^ 1);
        mv[j] = (float)m;
        pv[j] = m ? ns : 0.0f;
        nv[j] = m ? s_nsim[d0 + j] : 0.0f;
    }

    stg8_evict_first(pos_base + tid * 8, pv);
    stg8_evict_first(neg_base + tid * 8, nv);
    stg8_evict_first(msk_base + tid * 8, mv);
}

extern "C" void kernel_launch(void* const* d_in, const int* in_sizes, int n_in,
                              void* d_out, int out_size)
{
    (void)in_sizes; (void)n_in; (void)out_size;

    const float* semb    = (const float*)d_in[0];
    const int*   slabels = (const int*)  d_in[1];
    const int*   topk    = (const int*)  d_in[2];

    float* out = (float*)d_out;
    float* pos = out;
    float* neg = out + PAIR_ELEMS;
    float* msk = out + 2 * PAIR_ELEMS;
    float* nbr = out + 3 * PAIR_ELEMS;

    dim3 grid(PK * PB);   // 16384 CTAs
    dim3 block(128);
    distance_layer_kernel<<<grid, block>>>(semb, slabels, topk,
                                           pos, neg, msk, nbr);
}